// round 1
// baseline (speedup 1.0000x reference)
#include <cuda_runtime.h>

#define N_  2
#define T_  2048
#define D_  512
#define H_  8
#define HD_ 64
#define NTD (N_*T_*D_)          // 2097152 elements per stream output
#define NHTHD (N_*H_*T_*HD_)    // 2097152
#define PAD 68

// Scratch: [stream][q/k/v][n,h,t,hd]
__device__ float g_buf[2][3][NHTHD];
// softmaxed per-head scale: [stream][h*64+hd]
__device__ float g_sc[2][H_*HD_];

// ---------------------------------------------------------------------------
// Kernel 1: softmax of the (H,1,HD) scale params over HD (tiny)
// ---------------------------------------------------------------------------
__global__ void scale_kernel(const float* __restrict__ isc,
                             const float* __restrict__ lsc) {
    int i = threadIdx.x;
    if (i >= 16) return;
    int s = i >> 3, h = i & 7;
    const float* src = (s == 0 ? isc : lsc) + h * HD_;
    float m = -1e30f;
    for (int d = 0; d < HD_; d++) m = fmaxf(m, src[d]);
    float Z = 0.f;
    for (int d = 0; d < HD_; d++) Z += __expf(src[d] - m);
    float inv = 1.f / Z;
    for (int d = 0; d < HD_; d++) g_sc[s][h*HD_ + d] = __expf(src[d] - m) * inv;
}

// ---------------------------------------------------------------------------
// helpers
// ---------------------------------------------------------------------------
__device__ __forceinline__ void fma44(float (&acc)[4][4], float4 a, float4 b) {
    acc[0][0] += a.x*b.x; acc[0][1] += a.x*b.y; acc[0][2] += a.x*b.z; acc[0][3] += a.x*b.w;
    acc[1][0] += a.y*b.x; acc[1][1] += a.y*b.y; acc[1][2] += a.y*b.z; acc[1][3] += a.y*b.w;
    acc[2][0] += a.z*b.x; acc[2][1] += a.z*b.y; acc[2][2] += a.z*b.z; acc[2][3] += a.z*b.w;
    acc[3][0] += a.w*b.x; acc[3][1] += a.w*b.y; acc[3][2] += a.w*b.z; acc[3][3] += a.w*b.w;
}

__device__ __forceinline__ float red_max16(float v) {
    v = fmaxf(v, __shfl_xor_sync(0xffffffffu, v, 1));
    v = fmaxf(v, __shfl_xor_sync(0xffffffffu, v, 2));
    v = fmaxf(v, __shfl_xor_sync(0xffffffffu, v, 4));
    v = fmaxf(v, __shfl_xor_sync(0xffffffffu, v, 8));
    return v;
}
__device__ __forceinline__ float red_sum16(float v) {
    v += __shfl_xor_sync(0xffffffffu, v, 1);
    v += __shfl_xor_sync(0xffffffffu, v, 2);
    v += __shfl_xor_sync(0xffffffffu, v, 4);
    v += __shfl_xor_sync(0xffffffffu, v, 8);
    return v;
}

// ---------------------------------------------------------------------------
// Kernel 2: QKV GEMM  out[m,c] = sum_k z[m,k]*W[c,k], scatter to g_buf
// grid (1536/64, 4096/64), 256 threads, 64x64 tile, BK=32, 4x4 per thread
// ---------------------------------------------------------------------------
__global__ __launch_bounds__(256)
void qkv_kernel(const float* __restrict__ z, const float* __restrict__ W, int stream) {
    __shared__ float as[32][PAD];   // [k][m]
    __shared__ float bs[32][PAD];   // [k][c]
    int tid = threadIdx.x;
    int ty = tid >> 4, tx = tid & 15;
    int c0 = blockIdx.x * 64;
    int m0 = blockIdx.y * 64;

    float acc[4][4] = {};
    for (int k0 = 0; k0 < 512; k0 += 32) {
        __syncthreads();
        #pragma unroll
        for (int p = 0; p < 8; p++) {
            int idx = tid + p * 256;
            int mm = idx >> 5, kk = idx & 31;
            as[kk][mm] = z[(m0 + mm) * 512 + k0 + kk];
            bs[kk][mm] = W[(c0 + mm) * 512 + k0 + kk];
        }
        __syncthreads();
        #pragma unroll
        for (int k = 0; k < 32; k++) {
            float4 av = *(const float4*)&as[k][ty * 4];
            float4 bv = *(const float4*)&bs[k][tx * 4];
            fma44(acc, av, bv);
        }
    }

    int three = c0 >> 9;            // which of q/k/v (block is within one 64-col group)
    int h = (c0 >> 6) & 7;
    float* dst = g_buf[stream][three];
    bool isq = (three == 0);
    int hd = tx * 4;
    float4 s4 = make_float4(1.f, 1.f, 1.f, 1.f);
    if (isq) s4 = *(const float4*)&g_sc[stream][h * HD_ + hd];

    #pragma unroll
    for (int i = 0; i < 4; i++) {
        int mm = m0 + ty * 4 + i;
        int nn = mm >> 11, t = mm & 2047;
        float4 v = make_float4(acc[i][0] * s4.x, acc[i][1] * s4.y,
                               acc[i][2] * s4.z, acc[i][3] * s4.w);
        *(float4*)&dst[((nn * H_ + h) * T_ + t) * HD_ + hd] = v;
    }
}

// ---------------------------------------------------------------------------
// Kernel 3: fused dual attention.
// Block: one (stream, n, h, 64-row q-tile). 256 threads, 4x4 micro-tiles.
// anti = softmax(max(attn)-attn) == softmax(-attn) -> w = exp(-attn)/sum(w)
// ---------------------------------------------------------------------------
__global__ __launch_bounds__(256)
void attn_kernel(const float* __restrict__ sp, float* __restrict__ out) {
    extern __shared__ float smraw[];
    float (*qs)[PAD] = (float(*)[PAD])smraw;   // [d][r]
    float (*ks)[PAD] = qs + 64;                // [d][c]
    float (*vc)[PAD] = ks + 64;                // [c][dd] cross V
    float (*vf)[PAD] = vc + 64;                // [c][dd] self V
    float (*at)[PAD] = vf + 64;                // [c][r] attn
    float (*wt)[PAD] = at + 64;                // [c][r] anti weight

    int tid = threadIdx.x;
    int ty = tid >> 4, tx = tid & 15;
    int qt = blockIdx.x;
    int h  = blockIdx.y;
    int zb = blockIdx.z;
    int s  = zb >> 1, n = zb & 1;

    const float* Qb  = g_buf[s][0]     + ((n * H_ + h) * T_ + qt * 64) * HD_;
    const float* Kb  = g_buf[1 - s][1] + ((n * H_ + h) * T_) * HD_;
    const float* Vcb = g_buf[1 - s][2] + ((n * H_ + h) * T_) * HD_;
    const float* Vsb = g_buf[s][2]     + ((n * H_ + h) * T_) * HD_;
    float* ob = out + s * NTD;

    // load Q tile transposed [d][r]
    for (int idx = tid; idx < 64 * 64; idx += 256) {
        int r = idx >> 6, d = idx & 63;
        qs[d][r] = Qb[r * 64 + d];
    }

    float m[4], Zs[4];
    #pragma unroll
    for (int i = 0; i < 4; i++) { m[i] = -1e30f; Zs[i] = 0.f; }

    // ---- pass 1: softmax stats ----
    for (int kt = 0; kt < 32; kt++) {
        __syncthreads();
        for (int idx = tid; idx < 4096; idx += 256) {
            int c = idx >> 6, d = idx & 63;
            ks[d][c] = Kb[(kt * 64 + c) * 64 + d];
        }
        __syncthreads();
        float S[4][4] = {};
        #pragma unroll
        for (int d = 0; d < 64; d++) {
            float4 qv = *(const float4*)&qs[d][ty * 4];
            float4 kv = *(const float4*)&ks[d][tx * 4];
            fma44(S, qv, kv);
        }
        #pragma unroll
        for (int i = 0; i < 4; i++) {
            float tm = fmaxf(fmaxf(S[i][0], S[i][1]), fmaxf(S[i][2], S[i][3]));
            tm = red_max16(tm);
            float mn = fmaxf(m[i], tm);
            float ls = __expf(S[i][0] - mn) + __expf(S[i][1] - mn)
                     + __expf(S[i][2] - mn) + __expf(S[i][3] - mn);
            ls = red_sum16(ls);
            Zs[i] = Zs[i] * __expf(m[i] - mn) + ls;
            m[i] = mn;
        }
    }

    float invZ[4], sw[4];
    #pragma unroll
    for (int i = 0; i < 4; i++) { invZ[i] = 1.f / Zs[i]; sw[i] = 0.f; }

    float oc[4][4] = {}, os[4][4] = {};

    // ---- pass 2: attn + anti weights, two AV GEMMs ----
    for (int kt = 0; kt < 32; kt++) {
        __syncthreads();
        for (int idx = tid; idx < 4096; idx += 256) {
            int c = idx >> 6, d = idx & 63;
            int g = (kt * 64 + c) * 64 + d;
            ks[d][c] = Kb[g];
            vc[c][d] = Vcb[g];
            vf[c][d] = Vsb[g];
        }
        __syncthreads();
        float S[4][4] = {};
        #pragma unroll
        for (int d = 0; d < 64; d++) {
            float4 qv = *(const float4*)&qs[d][ty * 4];
            float4 kv = *(const float4*)&ks[d][tx * 4];
            fma44(S, qv, kv);
        }
        #pragma unroll
        for (int i = 0; i < 4; i++) {
            float lsw = 0.f;
            #pragma unroll
            for (int j = 0; j < 4; j++) {
                float a = __expf(S[i][j] - m[i]) * invZ[i];
                float w = __expf(-a);
                at[tx * 4 + j][ty * 4 + i] = a;
                wt[tx * 4 + j][ty * 4 + i] = w;
                lsw += w;
            }
            sw[i] += red_sum16(lsw);
        }
        __syncthreads();
        #pragma unroll
        for (int c = 0; c < 64; c++) {
            float4 a4  = *(const float4*)&at[c][ty * 4];
            float4 w4  = *(const float4*)&wt[c][ty * 4];
            float4 vcv = *(const float4*)&vc[c][tx * 4];
            float4 vfv = *(const float4*)&vf[c][tx * 4];
            fma44(oc, a4, vcv);
            fma44(os, w4, vfv);
        }
    }

    float spv = *sp;
    float oms = 1.0f - spv;
    #pragma unroll
    for (int i = 0; i < 4; i++) {
        int t = qt * 64 + ty * 4 + i;
        float invW = 1.f / sw[i];
        float4 o;
        o.x = spv * oc[i][0] + oms * os[i][0] * invW;
        o.y = spv * oc[i][1] + oms * os[i][1] * invW;
        o.z = spv * oc[i][2] + oms * os[i][2] * invW;
        o.w = spv * oc[i][3] + oms * os[i][3] * invW;
        *(float4*)&ob[(n * T_ + t) * D_ + h * HD_ + tx * 4] = o;
    }
}

// ---------------------------------------------------------------------------
extern "C" void kernel_launch(void* const* d_in, const int* in_sizes, int n_in,
                              void* d_out, int out_size) {
    const float* x   = (const float*)d_in[0];
    const float* y   = (const float*)d_in[1];
    const float* iw  = (const float*)d_in[2];
    const float* lw  = (const float*)d_in[3];
    const float* isc = (const float*)d_in[4];
    const float* lsc = (const float*)d_in[5];
    const float* sp  = (const float*)d_in[6];
    float* out = (float*)d_out;

    const int ATTN_SMEM = 6 * 64 * PAD * 4;   // 104448 bytes
    cudaFuncSetAttribute(attn_kernel, cudaFuncAttributeMaxDynamicSharedMemorySize, ATTN_SMEM);

    scale_kernel<<<1, 32>>>(isc, lsc);

    dim3 g1(1536 / 64, 4096 / 64);
    qkv_kernel<<<g1, 256>>>(x, iw, 0);
    qkv_kernel<<<g1, 256>>>(y, lw, 1);

    dim3 g2(T_ / 64, H_, 4);
    attn_kernel<<<g2, 256, ATTN_SMEM>>>(sp, out);
}